// round 12
// baseline (speedup 1.0000x reference)
#include <cuda_runtime.h>
#include <cuda_fp16.h>
#include <stdint.h>
#include <math.h>

#define BB 4
#define NN 2048
#define DIMM 1024
#define HH 16
#define DHH 64
#define SCALE 0.125f
#define MTOT (BB * NN) /* 8192 */
#define S72 72         /* smem row stride in fp16 (144 B, conflict-free ldmatrix) */

// ---------------- fp16 hi/lo split scratch ---------------------------------
__device__ __half g_zt_hi[MTOT * DIMM], g_zt_lo[MTOT * DIMM];    // [m, c]
__device__ __half g_w_hi[DIMM * DIMM], g_w_lo[DIMM * DIMM];      // [kp, c]
__device__ __half g_wt_hi[DIMM * DIMM], g_wt_lo[DIMM * DIMM];    // [c, kp]
__device__ __half g_ztu_hi[MTOT * DIMM], g_ztu_lo[MTOT * DIMM];  // [bh, n, d]
__device__ __half g_ssa_hi[MTOT * DIMM], g_ssa_lo[MTOT * DIMM];  // [m, k]

// ---------------- helpers ---------------------------------------------------
__device__ __forceinline__ uint32_t smem_u32(const void* p) {
    uint32_t a;
    asm("{ .reg .u64 t; cvta.to.shared.u64 t, %1; cvt.u32.u64 %0, t; }" : "=r"(a) : "l"(p));
    return a;
}
__device__ __forceinline__ void cp16(uint32_t dst, const void* src) {
    asm volatile("cp.async.cg.shared.global [%0], [%1], 16;" :: "r"(dst), "l"(src));
}
#define CP_COMMIT() asm volatile("cp.async.commit_group;" ::: "memory")
#define CP_WAIT1() asm volatile("cp.async.wait_group 1;" ::: "memory")
#define CP_WAIT0() asm volatile("cp.async.wait_group 0;" ::: "memory")

__device__ __forceinline__ void ldsm4(uint32_t& r0, uint32_t& r1, uint32_t& r2, uint32_t& r3,
                                      uint32_t addr) {
    asm volatile("ldmatrix.sync.aligned.m8n8.x4.shared.b16 {%0,%1,%2,%3},[%4];"
                 : "=r"(r0), "=r"(r1), "=r"(r2), "=r"(r3) : "r"(addr));
}
__device__ __forceinline__ void ldsm4t(uint32_t& r0, uint32_t& r1, uint32_t& r2, uint32_t& r3,
                                       uint32_t addr) {
    asm volatile("ldmatrix.sync.aligned.m8n8.x4.trans.shared.b16 {%0,%1,%2,%3},[%4];"
                 : "=r"(r0), "=r"(r1), "=r"(r2), "=r"(r3) : "r"(addr));
}
__device__ __forceinline__ void mma16816(float* c, const uint32_t* a, uint32_t b0, uint32_t b1) {
    asm volatile(
        "mma.sync.aligned.m16n8k16.row.col.f32.f16.f16.f32 "
        "{%0,%1,%2,%3},{%4,%5,%6,%7},{%8,%9},{%0,%1,%2,%3};"
        : "+f"(c[0]), "+f"(c[1]), "+f"(c[2]), "+f"(c[3])
        : "r"(a[0]), "r"(a[1]), "r"(a[2]), "r"(a[3]), "r"(b0), "r"(b1));
}
__device__ __forceinline__ uint32_t pkh(__half a, __half b) {
    return (uint32_t)__half_as_ushort(a) | ((uint32_t)__half_as_ushort(b) << 16);
}
__device__ __forceinline__ void split2(float x, float y, uint32_t& hi, uint32_t& lo) {
    __half hx = __float2half_rn(x), hy = __float2half_rn(y);
    hi = pkh(hx, hy);
    lo = pkh(__float2half_rn(x - __half2float(hx)), __float2half_rn(y - __half2float(hy)));
}
__device__ __forceinline__ uint32_t f2h2(float a, float b) {
    __half2 h = __floats2half2_rn(a, b);
    return *(uint32_t*)&h;
}
__device__ __forceinline__ uint32_t h2scale8(uint32_t x) {  // * 0.125 (exact)
    __half2 v = *(__half2*)&x;
    v = __hmul2(v, __float2half2_rn(0.125f));
    return *(uint32_t*)&v;
}

// ---------------- split kernels ---------------------------------------------
__global__ __launch_bounds__(256) void split_zt_kernel(const float* __restrict__ ZT) {
    size_t i = ((size_t)blockIdx.x * blockDim.x + threadIdx.x) * 4;
    float4 v = *(const float4*)(ZT + i);
    uint32_t h0, l0, h1, l1;
    split2(v.x, v.y, h0, l0);
    split2(v.z, v.w, h1, l1);
    *(uint2*)&g_zt_hi[i] = make_uint2(h0, h1);
    *(uint2*)&g_zt_lo[i] = make_uint2(l0, l1);
}

__global__ __launch_bounds__(1024) void split_w_kernel(const float* __restrict__ W) {
    __shared__ float t[32][33];
    int tx = threadIdx.x, ty = threadIdx.y;
    int k = blockIdx.y * 32 + ty, c = blockIdx.x * 32 + tx;
    float v = W[(size_t)k * DIMM + c];
    __half h = __float2half_rn(v);
    g_w_hi[(size_t)k * DIMM + c] = h;
    g_w_lo[(size_t)k * DIMM + c] = __float2half_rn(v - __half2float(h));
    t[ty][tx] = v;
    __syncthreads();
    int k2 = blockIdx.y * 32 + tx, c2 = blockIdx.x * 32 + ty;
    float v2 = t[tx][ty];
    __half h2 = __float2half_rn(v2);
    g_wt_hi[(size_t)c2 * DIMM + k2] = h2;
    g_wt_lo[(size_t)c2 * DIMM + k2] = __float2half_rn(v2 - __half2float(h2));
}

// ---------------- HMMA GEMM (3-stage cp.async pipeline, 256 thr) ------------
// Round-6 known-good body. 8 warps: (wm, wn) in 4x2, each 32x64 output tile.
#define G_TILE_B (128 * S72 * 2)   /* 18432 B per tile */
#define G_STAGE_B (4 * G_TILE_B)   /* Ah,Al,Bh,Bl */
#define GEMM_SMEM (3 * G_STAGE_B)  /* 221184 B */

template <int MODE>
__global__ __launch_bounds__(256) void gemm_hmma(float* __restrict__ outp) {
    extern __shared__ char sm[];
    const uint32_t aS = smem_u32(sm);
    const int tid = threadIdx.x, lane = tid & 31, wid = tid >> 5;
    const int wm = wid & 3, wn = wid >> 2;
    const int bm = blockIdx.y * 128, bn = blockIdx.x * 128;

    const __half* gp0 = ((MODE == 0) ? g_zt_hi : g_ssa_hi) + (size_t)bm * DIMM;
    const __half* gp1 = ((MODE == 0) ? g_zt_lo : g_ssa_lo) + (size_t)bm * DIMM;
    const __half* gp2 = ((MODE == 0) ? g_w_hi : g_wt_hi) + (size_t)bn * DIMM;
    const __half* gp3 = ((MODE == 0) ? g_w_lo : g_wt_lo) + (size_t)bn * DIMM;

    float c[2][8][4];
#pragma unroll
    for (int mi = 0; mi < 2; mi++)
#pragma unroll
        for (int nb = 0; nb < 8; nb++)
#pragma unroll
            for (int q = 0; q < 4; q++) c[mi][nb][q] = 0.f;

    // stage loader: 128 rows x 64 cols = 1024 16B-chunks per tile; 4 tiles.
    auto load_stage = [&](int st, int k0) {
        uint32_t sb = aS + (uint32_t)st * G_STAGE_B;
#pragma unroll
        for (int i = 0; i < 4; i++) {
            int idx = tid + i * 256;
            int r = idx >> 3, cc = (idx & 7) * 8;
            uint32_t so = (uint32_t)(r * S72 + cc) * 2;
            size_t go = (size_t)r * DIMM + k0 + cc;
            cp16(sb + 0 * G_TILE_B + so, gp0 + go);
            cp16(sb + 1 * G_TILE_B + so, gp1 + go);
            cp16(sb + 2 * G_TILE_B + so, gp2 + go);
            cp16(sb + 3 * G_TILE_B + so, gp3 + go);
        }
    };

    load_stage(0, 0);
    CP_COMMIT();

    for (int ch = 0; ch < 16; ch++) {
        if (ch + 1 < 16) {
            load_stage((ch + 1) % 3, (ch + 1) * 64);
            CP_COMMIT();
            CP_WAIT1();
        } else {
            CP_WAIT0();
        }
        __syncthreads();

        const uint32_t sb = aS + (uint32_t)(ch % 3) * G_STAGE_B;
        const uint32_t aAh = sb, aAl = sb + G_TILE_B;
        const uint32_t aBh = sb + 2 * G_TILE_B, aBl = sb + 3 * G_TILE_B;
#pragma unroll
        for (int kd = 0; kd < 4; kd++) {
            const uint32_t colb = (kd * 16 + ((lane >> 4) << 3)) * 2;
            uint32_t ah[2][4], al[2][4];
#pragma unroll
            for (int mi = 0; mi < 2; mi++) {
                uint32_t ro = (uint32_t)(wm * 32 + mi * 16 + (lane & 15)) * 144 + colb;
                ldsm4(ah[mi][0], ah[mi][1], ah[mi][2], ah[mi][3], aAh + ro);
                ldsm4(al[mi][0], al[mi][1], al[mi][2], al[mi][3], aAl + ro);
            }
            uint32_t bh[8][2], bl[8][2];
#pragma unroll
            for (int np = 0; np < 4; np++) {
                uint32_t ro = (uint32_t)(wn * 64 + np * 16 + (lane & 15)) * 144 + colb;
                uint32_t r0, r1, r2, r3;
                ldsm4(r0, r1, r2, r3, aBh + ro);
                bh[np * 2][0] = r0; bh[np * 2][1] = r2;
                bh[np * 2 + 1][0] = r1; bh[np * 2 + 1][1] = r3;
                ldsm4(r0, r1, r2, r3, aBl + ro);
                bl[np * 2][0] = r0; bl[np * 2][1] = r2;
                bl[np * 2 + 1][0] = r1; bl[np * 2 + 1][1] = r3;
            }
#pragma unroll
            for (int mi = 0; mi < 2; mi++)
#pragma unroll
                for (int nb = 0; nb < 8; nb++) {
                    mma16816(c[mi][nb], ah[mi], bh[nb][0], bh[nb][1]);
                    mma16816(c[mi][nb], ah[mi], bl[nb][0], bl[nb][1]);
                    mma16816(c[mi][nb], al[mi], bh[nb][0], bh[nb][1]);
                }
        }
        __syncthreads();
    }

    // epilogue
#pragma unroll
    for (int mi = 0; mi < 2; mi++) {
        const int m0 = bm + wm * 32 + mi * 16 + (lane >> 2);
#pragma unroll
        for (int nb = 0; nb < 8; nb++) {
            const int col = bn + wn * 64 + nb * 8 + 2 * (lane & 3);
            if (MODE == 0) {
                const int h = col >> 6, d = col & 63;
#pragma unroll
                for (int rr = 0; rr < 2; rr++) {
                    int m = m0 + rr * 8;
                    int b = m >> 11, n = m & 2047;
                    size_t base = (((size_t)(b * HH + h) * NN) + n) * DHH + d;
                    uint32_t hi, lo;
                    split2(c[mi][nb][rr * 2], c[mi][nb][rr * 2 + 1], hi, lo);
                    *(uint32_t*)&g_ztu_hi[base] = hi;
                    *(uint32_t*)&g_ztu_lo[base] = lo;
                }
            } else {
                *(float2*)&outp[(size_t)m0 * DIMM + col] = make_float2(c[mi][nb][0], c[mi][nb][1]);
                *(float2*)&outp[(size_t)(m0 + 8) * DIMM + col] = make_float2(c[mi][nb][2], c[mi][nb][3]);
            }
        }
    }
}

// ---------------- HMMA flash attention ---------------------------------------
// CTA: 64 q rows of one (b,h); 4 warps x m16; key chunks of 64. Q=K=V.
// 128 threads/CTA -> regfile allows 3 CTAs/SM (12 warps) at regs~133.
// NO Q smem: Q fragments loaded directly from global. Smem = 3-stage K ring.
#define A_KTILE_B (64 * S72 * 2)   /* 9216 B per tile */
#define A_KSTAGE_B (2 * A_KTILE_B) /* h + l */
#define ATTN_SMEM (3 * A_KSTAGE_B) /* 55296 B */
#define A_THREADS 128

__global__ __launch_bounds__(A_THREADS) void attn_hmma() {
    extern __shared__ char sm[];
    const uint32_t aK0 = smem_u32(sm);

    const int tid = threadIdx.x, lane = tid & 31, wid = tid >> 5;  // wid 0..3
    const int bh = blockIdx.y, q0 = blockIdx.x * 64;
    const __half* zh = g_ztu_hi + (size_t)bh * NN * DHH;
    const __half* zl = g_ztu_lo + (size_t)bh * NN * DHH;

    auto load_k = [&](int st, int j0) {
        uint32_t sb = aK0 + (uint32_t)st * A_KSTAGE_B;
#pragma unroll
        for (int i = 0; i < 4; i++) {
            int idx = tid + i * A_THREADS;
            int r = idx >> 3, cc = (idx & 7) * 8;
            uint32_t so = (uint32_t)(r * S72 + cc) * 2;
            size_t go = (size_t)(j0 + r) * DHH + cc;
            cp16(sb + so, zh + go);
            cp16(sb + A_KTILE_B + so, zl + go);
        }
    };
    load_k(0, 0);
    CP_COMMIT();

    // Q fragments directly from global; SCALE folded in (exact *2^-3).
    const int qrow = q0 + wid * 16 + (lane >> 2);
    uint32_t qh[4][4], ql[4][4];
#pragma unroll
    for (int kd = 0; kd < 4; kd++) {
        const int cb = kd * 16 + 2 * (lane & 3);
        qh[kd][0] = *(const uint32_t*)(zh + (size_t)qrow * DHH + cb);
        qh[kd][1] = *(const uint32_t*)(zh + (size_t)(qrow + 8) * DHH + cb);
        qh[kd][2] = *(const uint32_t*)(zh + (size_t)qrow * DHH + cb + 8);
        qh[kd][3] = *(const uint32_t*)(zh + (size_t)(qrow + 8) * DHH + cb + 8);
        ql[kd][0] = *(const uint32_t*)(zl + (size_t)qrow * DHH + cb);
        ql[kd][1] = *(const uint32_t*)(zl + (size_t)(qrow + 8) * DHH + cb);
        ql[kd][2] = *(const uint32_t*)(zl + (size_t)qrow * DHH + cb + 8);
        ql[kd][3] = *(const uint32_t*)(zl + (size_t)(qrow + 8) * DHH + cb + 8);
#pragma unroll
        for (int r = 0; r < 4; r++) {
            qh[kd][r] = h2scale8(qh[kd][r]);
            ql[kd][r] = h2scale8(ql[kd][r]);
        }
    }

    float o[8][4];
#pragma unroll
    for (int nb = 0; nb < 8; nb++)
#pragma unroll
        for (int q = 0; q < 4; q++) o[nb][q] = 0.f;
    float mr0 = -INFINITY, mr1 = -INFINITY, l0 = 0.f, l1 = 0.f;

    for (int ch = 0; ch < NN / 64; ch++) {
        if (ch + 1 < NN / 64) {
            load_k((ch + 1) % 3, (ch + 1) * 64);
            CP_COMMIT();
            CP_WAIT1();
        } else {
            CP_WAIT0();
        }
        __syncthreads();

        const uint32_t aKh = aK0 + (uint32_t)(ch % 3) * A_KSTAGE_B;
        const uint32_t aKl = aKh + A_KTILE_B;

        // S = (Q*SCALE) K^T  (16 x 64 per warp)
        float s[8][4];
#pragma unroll
        for (int nb = 0; nb < 8; nb++)
#pragma unroll
            for (int q = 0; q < 4; q++) s[nb][q] = 0.f;
#pragma unroll
        for (int kd = 0; kd < 4; kd++) {
            const uint32_t colb = (kd * 16 + ((lane >> 4) << 3)) * 2;
            uint32_t bhf[8][2], blf[8][2];
#pragma unroll
            for (int np = 0; np < 4; np++) {
                uint32_t ro = (uint32_t)(np * 16 + (lane & 15)) * 144 + colb;
                uint32_t r0, r1, r2, r3;
                ldsm4(r0, r1, r2, r3, aKh + ro);
                bhf[np * 2][0] = r0; bhf[np * 2][1] = r2;
                bhf[np * 2 + 1][0] = r1; bhf[np * 2 + 1][1] = r3;
                ldsm4(r0, r1, r2, r3, aKl + ro);
                blf[np * 2][0] = r0; blf[np * 2][1] = r2;
                blf[np * 2 + 1][0] = r1; blf[np * 2 + 1][1] = r3;
            }
#pragma unroll
            for (int nb = 0; nb < 8; nb++) {
                mma16816(s[nb], qh[kd], bhf[nb][0], bhf[nb][1]);
                mma16816(s[nb], qh[kd], blf[nb][0], blf[nb][1]);
                mma16816(s[nb], ql[kd], bhf[nb][0], bhf[nb][1]);
            }
        }

        // softmax (rows r=lane/4 and r+8)
        float t0 = -INFINITY, t1 = -INFINITY;
#pragma unroll
        for (int nb = 0; nb < 8; nb++) {
            t0 = fmaxf(t0, fmaxf(s[nb][0], s[nb][1]));
            t1 = fmaxf(t1, fmaxf(s[nb][2], s[nb][3]));
        }
        t0 = fmaxf(t0, __shfl_xor_sync(0xffffffffu, t0, 1));
        t0 = fmaxf(t0, __shfl_xor_sync(0xffffffffu, t0, 2));
        t1 = fmaxf(t1, __shfl_xor_sync(0xffffffffu, t1, 1));
        t1 = fmaxf(t1, __shfl_xor_sync(0xffffffffu, t1, 2));
        float mn0 = fmaxf(mr0, t0), mn1 = fmaxf(mr1, t1);
        float al0 = __expf(mr0 - mn0), al1 = __expf(mr1 - mn1);
        float ls0 = 0.f, ls1 = 0.f;
#pragma unroll
        for (int nb = 0; nb < 8; nb++) {
            s[nb][0] = __expf(s[nb][0] - mn0);
            s[nb][1] = __expf(s[nb][1] - mn0);
            s[nb][2] = __expf(s[nb][2] - mn1);
            s[nb][3] = __expf(s[nb][3] - mn1);
            ls0 += s[nb][0] + s[nb][1];
            ls1 += s[nb][2] + s[nb][3];
        }
        ls0 += __shfl_xor_sync(0xffffffffu, ls0, 1);
        ls0 += __shfl_xor_sync(0xffffffffu, ls0, 2);
        ls1 += __shfl_xor_sync(0xffffffffu, ls1, 1);
        ls1 += __shfl_xor_sync(0xffffffffu, ls1, 2);
        l0 = l0 * al0 + ls0;
        l1 = l1 * al1 + ls1;
        mr0 = mn0;
        mr1 = mn1;
#pragma unroll
        for (int nb = 0; nb < 8; nb++) {
            o[nb][0] *= al0; o[nb][1] *= al0;
            o[nb][2] *= al1; o[nb][3] *= al1;
        }

        // O += P_hi (V_hi + V_lo)   (V = same K tile, ldmatrix.trans)
#pragma unroll
        for (int kj = 0; kj < 4; kj++) {
            uint32_t pah[4];
            pah[0] = f2h2(s[2 * kj][0], s[2 * kj][1]);
            pah[1] = f2h2(s[2 * kj][2], s[2 * kj][3]);
            pah[2] = f2h2(s[2 * kj + 1][0], s[2 * kj + 1][1]);
            pah[3] = f2h2(s[2 * kj + 1][2], s[2 * kj + 1][3]);

            const uint32_t colb = ((lane >> 4) << 3) * 2;
            uint32_t vh[8][2], vl[8][2];
#pragma unroll
            for (int dp = 0; dp < 4; dp++) {
                uint32_t ro = (uint32_t)(kj * 16 + (lane & 15)) * 144 + dp * 32 + colb;
                uint32_t r0, r1, r2, r3;
                ldsm4t(r0, r1, r2, r3, aKh + ro);
                vh[dp * 2][0] = r0; vh[dp * 2][1] = r1;
                vh[dp * 2 + 1][0] = r2; vh[dp * 2 + 1][1] = r3;
                ldsm4t(r0, r1, r2, r3, aKl + ro);
                vl[dp * 2][0] = r0; vl[dp * 2][1] = r1;
                vl[dp * 2 + 1][0] = r2; vl[dp * 2 + 1][1] = r3;
            }
#pragma unroll
            for (int db = 0; db < 8; db++) {
                mma16816(o[db], pah, vh[db][0], vh[db][1]);
                mma16816(o[db], pah, vl[db][0], vl[db][1]);
            }
        }
    }

    // epilogue -> ssa hi/lo [b, n, h*64+d]
    const float inv0 = 1.f / l0, inv1 = 1.f / l1;
    const int b = bh >> 4, h = bh & 15;
    const int r0w = q0 + wid * 16 + (lane >> 2);
#pragma unroll
    for (int db = 0; db < 8; db++) {
        const int d = db * 8 + 2 * (lane & 3);
        size_t base0 = ((size_t)b * NN + r0w) * DIMM + h * DHH + d;
        size_t base1 = ((size_t)b * NN + r0w + 8) * DIMM + h * DHH + d;
        uint32_t hi, lo;
        split2(o[db][0] * inv0, o[db][1] * inv0, hi, lo);
        *(uint32_t*)&g_ssa_hi[base0] = hi;
        *(uint32_t*)&g_ssa_lo[base0] = lo;
        split2(o[db][2] * inv1, o[db][3] * inv1, hi, lo);
        *(uint32_t*)&g_ssa_hi[base1] = hi;
        *(uint32_t*)&g_ssa_lo[base1] = lo;
    }
}

// ---------------- launch -----------------------------------------------------
extern "C" void kernel_launch(void* const* d_in, const int* in_sizes, int n_in,
                              void* d_out, int out_size) {
    const float* ZT = (const float*)d_in[0];  // [B, N, DIM]
    const float* W = (const float*)d_in[1];   // [H*DH, DIM]
    float* out = (float*)d_out;               // [B, N, DIM]
    (void)in_sizes; (void)n_in; (void)out_size;

    cudaFuncSetAttribute(gemm_hmma<0>, cudaFuncAttributeMaxDynamicSharedMemorySize, GEMM_SMEM);
    cudaFuncSetAttribute(gemm_hmma<1>, cudaFuncAttributeMaxDynamicSharedMemorySize, GEMM_SMEM);
    cudaFuncSetAttribute(attn_hmma, cudaFuncAttributeMaxDynamicSharedMemorySize, ATTN_SMEM);

    split_zt_kernel<<<(MTOT * DIMM) / (256 * 4), 256>>>(ZT);
    split_w_kernel<<<dim3(32, 32), dim3(32, 32)>>>(W);
    gemm_hmma<0><<<dim3(DIMM / 128, MTOT / 128), 256, GEMM_SMEM>>>(nullptr);
    attn_hmma<<<dim3(NN / 64, BB * HH), A_THREADS, ATTN_SMEM>>>();
    gemm_hmma<1><<<dim3(DIMM / 128, MTOT / 128), 256, GEMM_SMEM>>>(out);
}

// round 13
// speedup vs baseline: 1.4210x; 1.4210x over previous
#include <cuda_runtime.h>
#include <cuda_fp16.h>
#include <stdint.h>
#include <math.h>

#define BB 4
#define NN 2048
#define DIMM 1024
#define HH 16
#define DHH 64
#define SCALE 0.125f
#define MTOT (BB * NN) /* 8192 */
#define S72 72         /* smem row stride in fp16 (144 B, conflict-free ldmatrix) */

// ---------------- fp16 scratch ----------------------------------------------
__device__ __half g_zt_hi[MTOT * DIMM], g_zt_lo[MTOT * DIMM];    // [m, c]
__device__ __half g_w_hi[DIMM * DIMM], g_w_lo[DIMM * DIMM];      // [kp, c]
__device__ __half g_wt_hi[DIMM * DIMM], g_wt_lo[DIMM * DIMM];    // [c, kp]
__device__ __half g_ztu[MTOT * DIMM];                            // [bh, n, d] fp16
__device__ __half g_ssa_hi[MTOT * DIMM], g_ssa_lo[MTOT * DIMM];  // [m, k]

// ---------------- helpers ---------------------------------------------------
__device__ __forceinline__ uint32_t smem_u32(const void* p) {
    uint32_t a;
    asm("{ .reg .u64 t; cvta.to.shared.u64 t, %1; cvt.u32.u64 %0, t; }" : "=r"(a) : "l"(p));
    return a;
}
__device__ __forceinline__ void cp16(uint32_t dst, const void* src) {
    asm volatile("cp.async.cg.shared.global [%0], [%1], 16;" :: "r"(dst), "l"(src));
}
#define CP_COMMIT() asm volatile("cp.async.commit_group;" ::: "memory")
#define CP_WAIT1() asm volatile("cp.async.wait_group 1;" ::: "memory")
#define CP_WAIT0() asm volatile("cp.async.wait_group 0;" ::: "memory")

__device__ __forceinline__ void ldsm4(uint32_t& r0, uint32_t& r1, uint32_t& r2, uint32_t& r3,
                                      uint32_t addr) {
    asm volatile("ldmatrix.sync.aligned.m8n8.x4.shared.b16 {%0,%1,%2,%3},[%4];"
                 : "=r"(r0), "=r"(r1), "=r"(r2), "=r"(r3) : "r"(addr));
}
__device__ __forceinline__ void ldsm4t(uint32_t& r0, uint32_t& r1, uint32_t& r2, uint32_t& r3,
                                       uint32_t addr) {
    asm volatile("ldmatrix.sync.aligned.m8n8.x4.trans.shared.b16 {%0,%1,%2,%3},[%4];"
                 : "=r"(r0), "=r"(r1), "=r"(r2), "=r"(r3) : "r"(addr));
}
__device__ __forceinline__ void mma16816(float* c, const uint32_t* a, uint32_t b0, uint32_t b1) {
    asm volatile(
        "mma.sync.aligned.m16n8k16.row.col.f32.f16.f16.f32 "
        "{%0,%1,%2,%3},{%4,%5,%6,%7},{%8,%9},{%0,%1,%2,%3};"
        : "+f"(c[0]), "+f"(c[1]), "+f"(c[2]), "+f"(c[3])
        : "r"(a[0]), "r"(a[1]), "r"(a[2]), "r"(a[3]), "r"(b0), "r"(b1));
}
__device__ __forceinline__ uint32_t pkh(__half a, __half b) {
    return (uint32_t)__half_as_ushort(a) | ((uint32_t)__half_as_ushort(b) << 16);
}
__device__ __forceinline__ void split2(float x, float y, uint32_t& hi, uint32_t& lo) {
    __half hx = __float2half_rn(x), hy = __float2half_rn(y);
    hi = pkh(hx, hy);
    lo = pkh(__float2half_rn(x - __half2float(hx)), __float2half_rn(y - __half2float(hy)));
}
__device__ __forceinline__ uint32_t f2h2(float a, float b) {
    __half2 h = __floats2half2_rn(a, b);
    return *(uint32_t*)&h;
}
__device__ __forceinline__ uint32_t h2scale8(uint32_t x) {  // * 0.125 (exact)
    __half2 v = *(__half2*)&x;
    v = __hmul2(v, __float2half2_rn(0.125f));
    return *(uint32_t*)&v;
}

// ---------------- split kernels ---------------------------------------------
__global__ __launch_bounds__(256) void split_zt_kernel(const float* __restrict__ ZT) {
    size_t i = ((size_t)blockIdx.x * blockDim.x + threadIdx.x) * 4;
    float4 v = *(const float4*)(ZT + i);
    uint32_t h0, l0, h1, l1;
    split2(v.x, v.y, h0, l0);
    split2(v.z, v.w, h1, l1);
    *(uint2*)&g_zt_hi[i] = make_uint2(h0, h1);
    *(uint2*)&g_zt_lo[i] = make_uint2(l0, l1);
}

__global__ __launch_bounds__(1024) void split_w_kernel(const float* __restrict__ W) {
    __shared__ float t[32][33];
    int tx = threadIdx.x, ty = threadIdx.y;
    int k = blockIdx.y * 32 + ty, c = blockIdx.x * 32 + tx;
    float v = W[(size_t)k * DIMM + c];
    __half h = __float2half_rn(v);
    g_w_hi[(size_t)k * DIMM + c] = h;
    g_w_lo[(size_t)k * DIMM + c] = __float2half_rn(v - __half2float(h));
    t[ty][tx] = v;
    __syncthreads();
    int k2 = blockIdx.y * 32 + tx, c2 = blockIdx.x * 32 + ty;
    float v2 = t[tx][ty];
    __half h2 = __float2half_rn(v2);
    g_wt_hi[(size_t)c2 * DIMM + k2] = h2;
    g_wt_lo[(size_t)c2 * DIMM + k2] = __float2half_rn(v2 - __half2float(h2));
}

// ---------------- HMMA GEMM (3-stage cp.async pipeline, 256 thr) ------------
// Round-6 known-good body. 8 warps: (wm, wn) in 4x2, each 32x64 output tile.
#define G_TILE_B (128 * S72 * 2)   /* 18432 B per tile */
#define G_STAGE_B (4 * G_TILE_B)   /* Ah,Al,Bh,Bl */
#define GEMM_SMEM (3 * G_STAGE_B)  /* 221184 B */

template <int MODE>
__global__ __launch_bounds__(256) void gemm_hmma(float* __restrict__ outp) {
    extern __shared__ char sm[];
    const uint32_t aS = smem_u32(sm);
    const int tid = threadIdx.x, lane = tid & 31, wid = tid >> 5;
    const int wm = wid & 3, wn = wid >> 2;
    const int bm = blockIdx.y * 128, bn = blockIdx.x * 128;

    const __half* gp0 = ((MODE == 0) ? g_zt_hi : g_ssa_hi) + (size_t)bm * DIMM;
    const __half* gp1 = ((MODE == 0) ? g_zt_lo : g_ssa_lo) + (size_t)bm * DIMM;
    const __half* gp2 = ((MODE == 0) ? g_w_hi : g_wt_hi) + (size_t)bn * DIMM;
    const __half* gp3 = ((MODE == 0) ? g_w_lo : g_wt_lo) + (size_t)bn * DIMM;

    float c[2][8][4];
#pragma unroll
    for (int mi = 0; mi < 2; mi++)
#pragma unroll
        for (int nb = 0; nb < 8; nb++)
#pragma unroll
            for (int q = 0; q < 4; q++) c[mi][nb][q] = 0.f;

    // stage loader: 128 rows x 64 cols = 1024 16B-chunks per tile; 4 tiles.
    auto load_stage = [&](int st, int k0) {
        uint32_t sb = aS + (uint32_t)st * G_STAGE_B;
#pragma unroll
        for (int i = 0; i < 4; i++) {
            int idx = tid + i * 256;
            int r = idx >> 3, cc = (idx & 7) * 8;
            uint32_t so = (uint32_t)(r * S72 + cc) * 2;
            size_t go = (size_t)r * DIMM + k0 + cc;
            cp16(sb + 0 * G_TILE_B + so, gp0 + go);
            cp16(sb + 1 * G_TILE_B + so, gp1 + go);
            cp16(sb + 2 * G_TILE_B + so, gp2 + go);
            cp16(sb + 3 * G_TILE_B + so, gp3 + go);
        }
    };

    load_stage(0, 0);
    CP_COMMIT();

    for (int ch = 0; ch < 16; ch++) {
        if (ch + 1 < 16) {
            load_stage((ch + 1) % 3, (ch + 1) * 64);
            CP_COMMIT();
            CP_WAIT1();
        } else {
            CP_WAIT0();
        }
        __syncthreads();

        const uint32_t sb = aS + (uint32_t)(ch % 3) * G_STAGE_B;
        const uint32_t aAh = sb, aAl = sb + G_TILE_B;
        const uint32_t aBh = sb + 2 * G_TILE_B, aBl = sb + 3 * G_TILE_B;
#pragma unroll
        for (int kd = 0; kd < 4; kd++) {
            const uint32_t colb = (kd * 16 + ((lane >> 4) << 3)) * 2;
            uint32_t ah[2][4], al[2][4];
#pragma unroll
            for (int mi = 0; mi < 2; mi++) {
                uint32_t ro = (uint32_t)(wm * 32 + mi * 16 + (lane & 15)) * 144 + colb;
                ldsm4(ah[mi][0], ah[mi][1], ah[mi][2], ah[mi][3], aAh + ro);
                ldsm4(al[mi][0], al[mi][1], al[mi][2], al[mi][3], aAl + ro);
            }
            uint32_t bh[8][2], bl[8][2];
#pragma unroll
            for (int np = 0; np < 4; np++) {
                uint32_t ro = (uint32_t)(wn * 64 + np * 16 + (lane & 15)) * 144 + colb;
                uint32_t r0, r1, r2, r3;
                ldsm4(r0, r1, r2, r3, aBh + ro);
                bh[np * 2][0] = r0; bh[np * 2][1] = r2;
                bh[np * 2 + 1][0] = r1; bh[np * 2 + 1][1] = r3;
                ldsm4(r0, r1, r2, r3, aBl + ro);
                bl[np * 2][0] = r0; bl[np * 2][1] = r2;
                bl[np * 2 + 1][0] = r1; bl[np * 2 + 1][1] = r3;
            }
#pragma unroll
            for (int mi = 0; mi < 2; mi++)
#pragma unroll
                for (int nb = 0; nb < 8; nb++) {
                    mma16816(c[mi][nb], ah[mi], bh[nb][0], bh[nb][1]);
                    mma16816(c[mi][nb], ah[mi], bl[nb][0], bl[nb][1]);
                    mma16816(c[mi][nb], al[mi], bh[nb][0], bh[nb][1]);
                }
        }
        __syncthreads();
    }

    // epilogue
#pragma unroll
    for (int mi = 0; mi < 2; mi++) {
        const int m0 = bm + wm * 32 + mi * 16 + (lane >> 2);
#pragma unroll
        for (int nb = 0; nb < 8; nb++) {
            const int col = bn + wn * 64 + nb * 8 + 2 * (lane & 3);
            if (MODE == 0) {
                const int h = col >> 6, d = col & 63;
#pragma unroll
                for (int rr = 0; rr < 2; rr++) {
                    int m = m0 + rr * 8;
                    int b = m >> 11, n = m & 2047;
                    size_t base = (((size_t)(b * HH + h) * NN) + n) * DHH + d;
                    *(uint32_t*)&g_ztu[base] =
                        f2h2(c[mi][nb][rr * 2], c[mi][nb][rr * 2 + 1]);
                }
            } else {
                *(float2*)&outp[(size_t)m0 * DIMM + col] = make_float2(c[mi][nb][0], c[mi][nb][1]);
                *(float2*)&outp[(size_t)(m0 + 8) * DIMM + col] = make_float2(c[mi][nb][2], c[mi][nb][3]);
            }
        }
    }
}

// ---------------- HMMA flash attention (fp16-only planes) --------------------
// CTA: 64 q rows of one (b,h); 4 warps x m16; key chunks of 64. Q=K=V=g_ztu.
// S = Q·K (fp16), PV = P·V (fp16); fp32 accum. Random per-key quantization
// errors average down ~sqrt(N_eff) through the softmax sum (measured: P-fp16
// already contributes only ~2e-5 to final rel_err).
#define A_KTILE_B (64 * S72 * 2)   /* 9216 B per tile */
#define ATTN_SMEM (3 * A_KTILE_B)  /* 27648 B, 3-stage ring */
#define A_THREADS 128

__global__ __launch_bounds__(A_THREADS) void attn_hmma() {
    extern __shared__ char sm[];
    const uint32_t aK0 = smem_u32(sm);

    const int tid = threadIdx.x, lane = tid & 31, wid = tid >> 5;  // wid 0..3
    const int bh = blockIdx.y, q0 = blockIdx.x * 64;
    const __half* z = g_ztu + (size_t)bh * NN * DHH;

    auto load_k = [&](int st, int j0) {
        uint32_t sb = aK0 + (uint32_t)st * A_KTILE_B;
#pragma unroll
        for (int i = 0; i < 4; i++) {
            int idx = tid + i * A_THREADS;
            int r = idx >> 3, cc = (idx & 7) * 8;
            cp16(sb + (uint32_t)(r * S72 + cc) * 2, z + (size_t)(j0 + r) * DHH + cc);
        }
    };
    load_k(0, 0);
    CP_COMMIT();

    // Q fragments directly from global; SCALE folded in (exact *2^-3).
    const int qrow = q0 + wid * 16 + (lane >> 2);
    uint32_t qf[4][4];
#pragma unroll
    for (int kd = 0; kd < 4; kd++) {
        const int cb = kd * 16 + 2 * (lane & 3);
        qf[kd][0] = *(const uint32_t*)(z + (size_t)qrow * DHH + cb);
        qf[kd][1] = *(const uint32_t*)(z + (size_t)(qrow + 8) * DHH + cb);
        qf[kd][2] = *(const uint32_t*)(z + (size_t)qrow * DHH + cb + 8);
        qf[kd][3] = *(const uint32_t*)(z + (size_t)(qrow + 8) * DHH + cb + 8);
#pragma unroll
        for (int r = 0; r < 4; r++) qf[kd][r] = h2scale8(qf[kd][r]);
    }

    float o[8][4];
#pragma unroll
    for (int nb = 0; nb < 8; nb++)
#pragma unroll
        for (int q = 0; q < 4; q++) o[nb][q] = 0.f;
    float mr0 = -INFINITY, mr1 = -INFINITY, l0 = 0.f, l1 = 0.f;

    for (int ch = 0; ch < NN / 64; ch++) {
        if (ch + 1 < NN / 64) {
            load_k((ch + 1) % 3, (ch + 1) * 64);
            CP_COMMIT();
            CP_WAIT1();
        } else {
            CP_WAIT0();
        }
        __syncthreads();

        const uint32_t aK = aK0 + (uint32_t)(ch % 3) * A_KTILE_B;

        // S = (Q*SCALE) K^T  (16 x 64 per warp)
        float s[8][4];
#pragma unroll
        for (int nb = 0; nb < 8; nb++)
#pragma unroll
            for (int q = 0; q < 4; q++) s[nb][q] = 0.f;
#pragma unroll
        for (int kd = 0; kd < 4; kd++) {
            const uint32_t colb = (kd * 16 + ((lane >> 4) << 3)) * 2;
            uint32_t bf[8][2];
#pragma unroll
            for (int np = 0; np < 4; np++) {
                uint32_t ro = (uint32_t)(np * 16 + (lane & 15)) * 144 + colb;
                uint32_t r0, r1, r2, r3;
                ldsm4(r0, r1, r2, r3, aK + ro);
                bf[np * 2][0] = r0; bf[np * 2][1] = r2;
                bf[np * 2 + 1][0] = r1; bf[np * 2 + 1][1] = r3;
            }
#pragma unroll
            for (int nb = 0; nb < 8; nb++)
                mma16816(s[nb], qf[kd], bf[nb][0], bf[nb][1]);
        }

        // softmax (rows r=lane/4 and r+8)
        float t0 = -INFINITY, t1 = -INFINITY;
#pragma unroll
        for (int nb = 0; nb < 8; nb++) {
            t0 = fmaxf(t0, fmaxf(s[nb][0], s[nb][1]));
            t1 = fmaxf(t1, fmaxf(s[nb][2], s[nb][3]));
        }
        t0 = fmaxf(t0, __shfl_xor_sync(0xffffffffu, t0, 1));
        t0 = fmaxf(t0, __shfl_xor_sync(0xffffffffu, t0, 2));
        t1 = fmaxf(t1, __shfl_xor_sync(0xffffffffu, t1, 1));
        t1 = fmaxf(t1, __shfl_xor_sync(0xffffffffu, t1, 2));
        float mn0 = fmaxf(mr0, t0), mn1 = fmaxf(mr1, t1);
        float al0 = __expf(mr0 - mn0), al1 = __expf(mr1 - mn1);
        float ls0 = 0.f, ls1 = 0.f;
#pragma unroll
        for (int nb = 0; nb < 8; nb++) {
            s[nb][0] = __expf(s[nb][0] - mn0);
            s[nb][1] = __expf(s[nb][1] - mn0);
            s[nb][2] = __expf(s[nb][2] - mn1);
            s[nb][3] = __expf(s[nb][3] - mn1);
            ls0 += s[nb][0] + s[nb][1];
            ls1 += s[nb][2] + s[nb][3];
        }
        ls0 += __shfl_xor_sync(0xffffffffu, ls0, 1);
        ls0 += __shfl_xor_sync(0xffffffffu, ls0, 2);
        ls1 += __shfl_xor_sync(0xffffffffu, ls1, 1);
        ls1 += __shfl_xor_sync(0xffffffffu, ls1, 2);
        l0 = l0 * al0 + ls0;
        l1 = l1 * al1 + ls1;
        mr0 = mn0;
        mr1 = mn1;
#pragma unroll
        for (int nb = 0; nb < 8; nb++) {
            o[nb][0] *= al0; o[nb][1] *= al0;
            o[nb][2] *= al1; o[nb][3] *= al1;
        }

        // O += P V  (V = same K tile, ldmatrix.trans)
#pragma unroll
        for (int kj = 0; kj < 4; kj++) {
            uint32_t pa[4];
            pa[0] = f2h2(s[2 * kj][0], s[2 * kj][1]);
            pa[1] = f2h2(s[2 * kj][2], s[2 * kj][3]);
            pa[2] = f2h2(s[2 * kj + 1][0], s[2 * kj + 1][1]);
            pa[3] = f2h2(s[2 * kj + 1][2], s[2 * kj + 1][3]);

            const uint32_t colb = ((lane >> 4) << 3) * 2;
            uint32_t vf[8][2];
#pragma unroll
            for (int dp = 0; dp < 4; dp++) {
                uint32_t ro = (uint32_t)(kj * 16 + (lane & 15)) * 144 + dp * 32 + colb;
                uint32_t r0, r1, r2, r3;
                ldsm4t(r0, r1, r2, r3, aK + ro);
                vf[dp * 2][0] = r0; vf[dp * 2][1] = r1;
                vf[dp * 2 + 1][0] = r2; vf[dp * 2 + 1][1] = r3;
            }
#pragma unroll
            for (int db = 0; db < 8; db++)
                mma16816(o[db], pa, vf[db][0], vf[db][1]);
        }
    }

    // epilogue -> ssa hi/lo [b, n, h*64+d]  (hi/lo kept: GEMM2 path has no
    // error averaging, so SSA must stay split-precision)
    const float inv0 = 1.f / l0, inv1 = 1.f / l1;
    const int b = bh >> 4, h = bh & 15;
    const int r0w = q0 + wid * 16 + (lane >> 2);
#pragma unroll
    for (int db = 0; db < 8; db++) {
        const int d = db * 8 + 2 * (lane & 3);
        size_t base0 = ((size_t)b * NN + r0w) * DIMM + h * DHH + d;
        size_t base1 = ((size_t)b * NN + r0w + 8) * DIMM + h * DHH + d;
        uint32_t hi, lo;
        split2(o[db][0] * inv0, o[db][1] * inv0, hi, lo);
        *(uint32_t*)&g_ssa_hi[base0] = hi;
        *(uint32_t*)&g_ssa_lo[base0] = lo;
        split2(o[db][2] * inv1, o[db][3] * inv1, hi, lo);
        *(uint32_t*)&g_ssa_hi[base1] = hi;
        *(uint32_t*)&g_ssa_lo[base1] = lo;
    }
}

// ---------------- launch -----------------------------------------------------
extern "C" void kernel_launch(void* const* d_in, const int* in_sizes, int n_in,
                              void* d_out, int out_size) {
    const float* ZT = (const float*)d_in[0];  // [B, N, DIM]
    const float* W = (const float*)d_in[1];   // [H*DH, DIM]
    float* out = (float*)d_out;               // [B, N, DIM]
    (void)in_sizes; (void)n_in; (void)out_size;

    cudaFuncSetAttribute(gemm_hmma<0>, cudaFuncAttributeMaxDynamicSharedMemorySize, GEMM_SMEM);
    cudaFuncSetAttribute(gemm_hmma<1>, cudaFuncAttributeMaxDynamicSharedMemorySize, GEMM_SMEM);
    cudaFuncSetAttribute(attn_hmma, cudaFuncAttributeMaxDynamicSharedMemorySize, ATTN_SMEM);

    split_zt_kernel<<<(MTOT * DIMM) / (256 * 4), 256>>>(ZT);
    split_w_kernel<<<dim3(32, 32), dim3(32, 32)>>>(W);
    gemm_hmma<0><<<dim3(DIMM / 128, MTOT / 128), 256, GEMM_SMEM>>>(nullptr);
    attn_hmma<<<dim3(NN / 64, BB * HH), A_THREADS, ATTN_SMEM>>>();
    gemm_hmma<1><<<dim3(DIMM / 128, MTOT / 128), 256, GEMM_SMEM>>>(out);
}

// round 14
// speedup vs baseline: 1.6277x; 1.1454x over previous
#include <cuda_runtime.h>
#include <cuda_fp16.h>
#include <stdint.h>
#include <math.h>

#define BB 4
#define NN 2048
#define DIMM 1024
#define HH 16
#define DHH 64
#define SCALE 0.125f
#define MTOT (BB * NN) /* 8192 */
#define S72 72         /* smem row stride in fp16 (144 B, conflict-free ldmatrix) */

// ---------------- fp16 scratch ----------------------------------------------
__device__ __half g_zt[MTOT * DIMM];                             // [m, c] fp16
__device__ __half g_w_hi[DIMM * DIMM], g_w_lo[DIMM * DIMM];      // [kp, c]
__device__ __half g_wt_hi[DIMM * DIMM], g_wt_lo[DIMM * DIMM];    // [c, kp]
__device__ __half g_ztu[MTOT * DIMM];                            // [bh, n, d] fp16
__device__ __half g_ssa_hi[MTOT * DIMM], g_ssa_lo[MTOT * DIMM];  // [m, k]

// ---------------- helpers ---------------------------------------------------
__device__ __forceinline__ uint32_t smem_u32(const void* p) {
    uint32_t a;
    asm("{ .reg .u64 t; cvta.to.shared.u64 t, %1; cvt.u32.u64 %0, t; }" : "=r"(a) : "l"(p));
    return a;
}
__device__ __forceinline__ void cp16(uint32_t dst, const void* src) {
    asm volatile("cp.async.cg.shared.global [%0], [%1], 16;" :: "r"(dst), "l"(src));
}
#define CP_COMMIT() asm volatile("cp.async.commit_group;" ::: "memory")
#define CP_WAIT1() asm volatile("cp.async.wait_group 1;" ::: "memory")
#define CP_WAIT0() asm volatile("cp.async.wait_group 0;" ::: "memory")

__device__ __forceinline__ void ldsm4(uint32_t& r0, uint32_t& r1, uint32_t& r2, uint32_t& r3,
                                      uint32_t addr) {
    asm volatile("ldmatrix.sync.aligned.m8n8.x4.shared.b16 {%0,%1,%2,%3},[%4];"
                 : "=r"(r0), "=r"(r1), "=r"(r2), "=r"(r3) : "r"(addr));
}
__device__ __forceinline__ void ldsm4t(uint32_t& r0, uint32_t& r1, uint32_t& r2, uint32_t& r3,
                                       uint32_t addr) {
    asm volatile("ldmatrix.sync.aligned.m8n8.x4.trans.shared.b16 {%0,%1,%2,%3},[%4];"
                 : "=r"(r0), "=r"(r1), "=r"(r2), "=r"(r3) : "r"(addr));
}
__device__ __forceinline__ void mma16816(float* c, const uint32_t* a, uint32_t b0, uint32_t b1) {
    asm volatile(
        "mma.sync.aligned.m16n8k16.row.col.f32.f16.f16.f32 "
        "{%0,%1,%2,%3},{%4,%5,%6,%7},{%8,%9},{%0,%1,%2,%3};"
        : "+f"(c[0]), "+f"(c[1]), "+f"(c[2]), "+f"(c[3])
        : "r"(a[0]), "r"(a[1]), "r"(a[2]), "r"(a[3]), "r"(b0), "r"(b1));
}
__device__ __forceinline__ uint32_t pkh(__half a, __half b) {
    return (uint32_t)__half_as_ushort(a) | ((uint32_t)__half_as_ushort(b) << 16);
}
__device__ __forceinline__ void split2(float x, float y, uint32_t& hi, uint32_t& lo) {
    __half hx = __float2half_rn(x), hy = __float2half_rn(y);
    hi = pkh(hx, hy);
    lo = pkh(__float2half_rn(x - __half2float(hx)), __float2half_rn(y - __half2float(hy)));
}
__device__ __forceinline__ uint32_t f2h2(float a, float b) {
    __half2 h = __floats2half2_rn(a, b);
    return *(uint32_t*)&h;
}
__device__ __forceinline__ uint32_t h2scale8(uint32_t x) {  // * 0.125 (exact)
    __half2 v = *(__half2*)&x;
    v = __hmul2(v, __float2half2_rn(0.125f));
    return *(uint32_t*)&v;
}

// ---------------- split kernels ---------------------------------------------
__global__ __launch_bounds__(256) void split_zt_kernel(const float* __restrict__ ZT) {
    size_t i = ((size_t)blockIdx.x * blockDim.x + threadIdx.x) * 4;
    float4 v = *(const float4*)(ZT + i);
    *(uint2*)&g_zt[i] = make_uint2(f2h2(v.x, v.y), f2h2(v.z, v.w));
}

__global__ __launch_bounds__(1024) void split_w_kernel(const float* __restrict__ W) {
    __shared__ float t[32][33];
    int tx = threadIdx.x, ty = threadIdx.y;
    int k = blockIdx.y * 32 + ty, c = blockIdx.x * 32 + tx;
    float v = W[(size_t)k * DIMM + c];
    __half h = __float2half_rn(v);
    g_w_hi[(size_t)k * DIMM + c] = h;
    g_w_lo[(size_t)k * DIMM + c] = __float2half_rn(v - __half2float(h));
    t[ty][tx] = v;
    __syncthreads();
    int k2 = blockIdx.y * 32 + tx, c2 = blockIdx.x * 32 + ty;
    float v2 = t[tx][ty];
    __half h2 = __float2half_rn(v2);
    g_wt_hi[(size_t)c2 * DIMM + k2] = h2;
    g_wt_lo[(size_t)c2 * DIMM + k2] = __float2half_rn(v2 - __half2float(h2));
}

#define G_TILE_B (128 * S72 * 2)   /* 18432 B per tile */

// ---------------- GEMM1: ZTU = ZT·W^T (2-term, 2-stage, 2 CTAs/SM) ----------
// A = zt fp16 (no residual); B = w hi/lo. Terms: a·bh + a·bl.
#define G1_STAGE_B (3 * G_TILE_B)   /* A, Bh, Bl */
#define GEMM1_SMEM (2 * G1_STAGE_B) /* 110592 B -> 2 CTAs/SM */

__global__ __launch_bounds__(256) void gemm1_hmma() {
    extern __shared__ char sm[];
    const uint32_t aS = smem_u32(sm);
    const int tid = threadIdx.x, lane = tid & 31, wid = tid >> 5;
    const int wm = wid & 3, wn = wid >> 2;
    const int bm = blockIdx.y * 128, bn = blockIdx.x * 128;

    const __half* gpA = g_zt + (size_t)bm * DIMM;
    const __half* gpBh = g_w_hi + (size_t)bn * DIMM;
    const __half* gpBl = g_w_lo + (size_t)bn * DIMM;

    float c[2][8][4];
#pragma unroll
    for (int mi = 0; mi < 2; mi++)
#pragma unroll
        for (int nb = 0; nb < 8; nb++)
#pragma unroll
            for (int q = 0; q < 4; q++) c[mi][nb][q] = 0.f;

    auto load_stage = [&](int st, int k0) {
        uint32_t sb = aS + (uint32_t)st * G1_STAGE_B;
#pragma unroll
        for (int i = 0; i < 4; i++) {
            int idx = tid + i * 256;
            int r = idx >> 3, cc = (idx & 7) * 8;
            uint32_t so = (uint32_t)(r * S72 + cc) * 2;
            size_t go = (size_t)r * DIMM + k0 + cc;
            cp16(sb + 0 * G_TILE_B + so, gpA + go);
            cp16(sb + 1 * G_TILE_B + so, gpBh + go);
            cp16(sb + 2 * G_TILE_B + so, gpBl + go);
        }
    };

    load_stage(0, 0);
    CP_COMMIT();

    for (int ch = 0; ch < 16; ch++) {
        if (ch + 1 < 16) {
            load_stage((ch + 1) & 1, (ch + 1) * 64);
            CP_COMMIT();
            CP_WAIT1();
        } else {
            CP_WAIT0();
        }
        __syncthreads();

        const uint32_t sb = aS + (uint32_t)(ch & 1) * G1_STAGE_B;
        const uint32_t aA = sb, aBh = sb + G_TILE_B, aBl = sb + 2 * G_TILE_B;
#pragma unroll
        for (int kd = 0; kd < 4; kd++) {
            const uint32_t colb = (kd * 16 + ((lane >> 4) << 3)) * 2;
            uint32_t af[2][4];
#pragma unroll
            for (int mi = 0; mi < 2; mi++) {
                uint32_t ro = (uint32_t)(wm * 32 + mi * 16 + (lane & 15)) * 144 + colb;
                ldsm4(af[mi][0], af[mi][1], af[mi][2], af[mi][3], aA + ro);
            }
            uint32_t bh[8][2], bl[8][2];
#pragma unroll
            for (int np = 0; np < 4; np++) {
                uint32_t ro = (uint32_t)(wn * 64 + np * 16 + (lane & 15)) * 144 + colb;
                uint32_t r0, r1, r2, r3;
                ldsm4(r0, r1, r2, r3, aBh + ro);
                bh[np * 2][0] = r0; bh[np * 2][1] = r2;
                bh[np * 2 + 1][0] = r1; bh[np * 2 + 1][1] = r3;
                ldsm4(r0, r1, r2, r3, aBl + ro);
                bl[np * 2][0] = r0; bl[np * 2][1] = r2;
                bl[np * 2 + 1][0] = r1; bl[np * 2 + 1][1] = r3;
            }
#pragma unroll
            for (int mi = 0; mi < 2; mi++)
#pragma unroll
                for (int nb = 0; nb < 8; nb++) {
                    mma16816(c[mi][nb], af[mi], bh[nb][0], bh[nb][1]);
                    mma16816(c[mi][nb], af[mi], bl[nb][0], bl[nb][1]);
                }
        }
        __syncthreads();
    }

    // epilogue -> g_ztu fp16 scatter [bh, n, d]
#pragma unroll
    for (int mi = 0; mi < 2; mi++) {
        const int m0 = bm + wm * 32 + mi * 16 + (lane >> 2);
#pragma unroll
        for (int nb = 0; nb < 8; nb++) {
            const int col = bn + wn * 64 + nb * 8 + 2 * (lane & 3);
            const int h = col >> 6, d = col & 63;
#pragma unroll
            for (int rr = 0; rr < 2; rr++) {
                int m = m0 + rr * 8;
                int b = m >> 11, n = m & 2047;
                size_t base = (((size_t)(b * HH + h) * NN) + n) * DHH + d;
                *(uint32_t*)&g_ztu[base] = f2h2(c[mi][nb][rr * 2], c[mi][nb][rr * 2 + 1]);
            }
        }
    }
}

// ---------------- GEMM2: out = SSA·W (3-term, round-6 known-good body) ------
#define G_STAGE_B (4 * G_TILE_B)   /* Ah,Al,Bh,Bl */
#define GEMM_SMEM (3 * G_STAGE_B)  /* 221184 B */

__global__ __launch_bounds__(256) void gemm2_hmma(float* __restrict__ outp) {
    extern __shared__ char sm[];
    const uint32_t aS = smem_u32(sm);
    const int tid = threadIdx.x, lane = tid & 31, wid = tid >> 5;
    const int wm = wid & 3, wn = wid >> 2;
    const int bm = blockIdx.y * 128, bn = blockIdx.x * 128;

    const __half* gp0 = g_ssa_hi + (size_t)bm * DIMM;
    const __half* gp1 = g_ssa_lo + (size_t)bm * DIMM;
    const __half* gp2 = g_wt_hi + (size_t)bn * DIMM;
    const __half* gp3 = g_wt_lo + (size_t)bn * DIMM;

    float c[2][8][4];
#pragma unroll
    for (int mi = 0; mi < 2; mi++)
#pragma unroll
        for (int nb = 0; nb < 8; nb++)
#pragma unroll
            for (int q = 0; q < 4; q++) c[mi][nb][q] = 0.f;

    auto load_stage = [&](int st, int k0) {
        uint32_t sb = aS + (uint32_t)st * G_STAGE_B;
#pragma unroll
        for (int i = 0; i < 4; i++) {
            int idx = tid + i * 256;
            int r = idx >> 3, cc = (idx & 7) * 8;
            uint32_t so = (uint32_t)(r * S72 + cc) * 2;
            size_t go = (size_t)r * DIMM + k0 + cc;
            cp16(sb + 0 * G_TILE_B + so, gp0 + go);
            cp16(sb + 1 * G_TILE_B + so, gp1 + go);
            cp16(sb + 2 * G_TILE_B + so, gp2 + go);
            cp16(sb + 3 * G_TILE_B + so, gp3 + go);
        }
    };

    load_stage(0, 0);
    CP_COMMIT();

    for (int ch = 0; ch < 16; ch++) {
        if (ch + 1 < 16) {
            load_stage((ch + 1) % 3, (ch + 1) * 64);
            CP_COMMIT();
            CP_WAIT1();
        } else {
            CP_WAIT0();
        }
        __syncthreads();

        const uint32_t sb = aS + (uint32_t)(ch % 3) * G_STAGE_B;
        const uint32_t aAh = sb, aAl = sb + G_TILE_B;
        const uint32_t aBh = sb + 2 * G_TILE_B, aBl = sb + 3 * G_TILE_B;
#pragma unroll
        for (int kd = 0; kd < 4; kd++) {
            const uint32_t colb = (kd * 16 + ((lane >> 4) << 3)) * 2;
            uint32_t ah[2][4], al[2][4];
#pragma unroll
            for (int mi = 0; mi < 2; mi++) {
                uint32_t ro = (uint32_t)(wm * 32 + mi * 16 + (lane & 15)) * 144 + colb;
                ldsm4(ah[mi][0], ah[mi][1], ah[mi][2], ah[mi][3], aAh + ro);
                ldsm4(al[mi][0], al[mi][1], al[mi][2], al[mi][3], aAl + ro);
            }
            uint32_t bh[8][2], bl[8][2];
#pragma unroll
            for (int np = 0; np < 4; np++) {
                uint32_t ro = (uint32_t)(wn * 64 + np * 16 + (lane & 15)) * 144 + colb;
                uint32_t r0, r1, r2, r3;
                ldsm4(r0, r1, r2, r3, aBh + ro);
                bh[np * 2][0] = r0; bh[np * 2][1] = r2;
                bh[np * 2 + 1][0] = r1; bh[np * 2 + 1][1] = r3;
                ldsm4(r0, r1, r2, r3, aBl + ro);
                bl[np * 2][0] = r0; bl[np * 2][1] = r2;
                bl[np * 2 + 1][0] = r1; bl[np * 2 + 1][1] = r3;
            }
#pragma unroll
            for (int mi = 0; mi < 2; mi++)
#pragma unroll
                for (int nb = 0; nb < 8; nb++) {
                    mma16816(c[mi][nb], ah[mi], bh[nb][0], bh[nb][1]);
                    mma16816(c[mi][nb], ah[mi], bl[nb][0], bl[nb][1]);
                    mma16816(c[mi][nb], al[mi], bh[nb][0], bh[nb][1]);
                }
        }
        __syncthreads();
    }

#pragma unroll
    for (int mi = 0; mi < 2; mi++) {
        const int m0 = bm + wm * 32 + mi * 16 + (lane >> 2);
#pragma unroll
        for (int nb = 0; nb < 8; nb++) {
            const int col = bn + wn * 64 + nb * 8 + 2 * (lane & 3);
            *(float2*)&outp[(size_t)m0 * DIMM + col] = make_float2(c[mi][nb][0], c[mi][nb][1]);
            *(float2*)&outp[(size_t)(m0 + 8) * DIMM + col] = make_float2(c[mi][nb][2], c[mi][nb][3]);
        }
    }
}

// ---------------- HMMA flash attention (fp16 planes, round-13 body) ---------
#define A_KTILE_B (64 * S72 * 2)   /* 9216 B per tile */
#define ATTN_SMEM (3 * A_KTILE_B)  /* 27648 B, 3-stage ring */
#define A_THREADS 128

__global__ __launch_bounds__(A_THREADS) void attn_hmma() {
    extern __shared__ char sm[];
    const uint32_t aK0 = smem_u32(sm);

    const int tid = threadIdx.x, lane = tid & 31, wid = tid >> 5;  // wid 0..3
    const int bh = blockIdx.y, q0 = blockIdx.x * 64;
    const __half* z = g_ztu + (size_t)bh * NN * DHH;

    auto load_k = [&](int st, int j0) {
        uint32_t sb = aK0 + (uint32_t)st * A_KTILE_B;
#pragma unroll
        for (int i = 0; i < 4; i++) {
            int idx = tid + i * A_THREADS;
            int r = idx >> 3, cc = (idx & 7) * 8;
            cp16(sb + (uint32_t)(r * S72 + cc) * 2, z + (size_t)(j0 + r) * DHH + cc);
        }
    };
    load_k(0, 0);
    CP_COMMIT();

    const int qrow = q0 + wid * 16 + (lane >> 2);
    uint32_t qf[4][4];
#pragma unroll
    for (int kd = 0; kd < 4; kd++) {
        const int cb = kd * 16 + 2 * (lane & 3);
        qf[kd][0] = *(const uint32_t*)(z + (size_t)qrow * DHH + cb);
        qf[kd][1] = *(const uint32_t*)(z + (size_t)(qrow + 8) * DHH + cb);
        qf[kd][2] = *(const uint32_t*)(z + (size_t)qrow * DHH + cb + 8);
        qf[kd][3] = *(const uint32_t*)(z + (size_t)(qrow + 8) * DHH + cb + 8);
#pragma unroll
        for (int r = 0; r < 4; r++) qf[kd][r] = h2scale8(qf[kd][r]);
    }

    float o[8][4];
#pragma unroll
    for (int nb = 0; nb < 8; nb++)
#pragma unroll
        for (int q = 0; q < 4; q++) o[nb][q] = 0.f;
    float mr0 = -INFINITY, mr1 = -INFINITY, l0 = 0.f, l1 = 0.f;

    for (int ch = 0; ch < NN / 64; ch++) {
        if (ch + 1 < NN / 64) {
            load_k((ch + 1) % 3, (ch + 1) * 64);
            CP_COMMIT();
            CP_WAIT1();
        } else {
            CP_WAIT0();
        }
        __syncthreads();

        const uint32_t aK = aK0 + (uint32_t)(ch % 3) * A_KTILE_B;

        float s[8][4];
#pragma unroll
        for (int nb = 0; nb < 8; nb++)
#pragma unroll
            for (int q = 0; q < 4; q++) s[nb][q] = 0.f;
#pragma unroll
        for (int kd = 0; kd < 4; kd++) {
            const uint32_t colb = (kd * 16 + ((lane >> 4) << 3)) * 2;
            uint32_t bf[8][2];
#pragma unroll
            for (int np = 0; np < 4; np++) {
                uint32_t ro = (uint32_t)(np * 16 + (lane & 15)) * 144 + colb;
                uint32_t r0, r1, r2, r3;
                ldsm4(r0, r1, r2, r3, aK + ro);
                bf[np * 2][0] = r0; bf[np * 2][1] = r2;
                bf[np * 2 + 1][0] = r1; bf[np * 2 + 1][1] = r3;
            }
#pragma unroll
            for (int nb = 0; nb < 8; nb++)
                mma16816(s[nb], qf[kd], bf[nb][0], bf[nb][1]);
        }

        float t0 = -INFINITY, t1 = -INFINITY;
#pragma unroll
        for (int nb = 0; nb < 8; nb++) {
            t0 = fmaxf(t0, fmaxf(s[nb][0], s[nb][1]));
            t1 = fmaxf(t1, fmaxf(s[nb][2], s[nb][3]));
        }
        t0 = fmaxf(t0, __shfl_xor_sync(0xffffffffu, t0, 1));
        t0 = fmaxf(t0, __shfl_xor_sync(0xffffffffu, t0, 2));
        t1 = fmaxf(t1, __shfl_xor_sync(0xffffffffu, t1, 1));
        t1 = fmaxf(t1, __shfl_xor_sync(0xffffffffu, t1, 2));
        float mn0 = fmaxf(mr0, t0), mn1 = fmaxf(mr1, t1);
        float al0 = __expf(mr0 - mn0), al1 = __expf(mr1 - mn1);
        float ls0 = 0.f, ls1 = 0.f;
#pragma unroll
        for (int nb = 0; nb < 8; nb++) {
            s[nb][0] = __expf(s[nb][0] - mn0);
            s[nb][1] = __expf(s[nb][1] - mn0);
            s[nb][2] = __expf(s[nb][2] - mn1);
            s[nb][3] = __expf(s[nb][3] - mn1);
            ls0 += s[nb][0] + s[nb][1];
            ls1 += s[nb][2] + s[nb][3];
        }
        ls0 += __shfl_xor_sync(0xffffffffu, ls0, 1);
        ls0 += __shfl_xor_sync(0xffffffffu, ls0, 2);
        ls1 += __shfl_xor_sync(0xffffffffu, ls1, 1);
        ls1 += __shfl_xor_sync(0xffffffffu, ls1, 2);
        l0 = l0 * al0 + ls0;
        l1 = l1 * al1 + ls1;
        mr0 = mn0;
        mr1 = mn1;
#pragma unroll
        for (int nb = 0; nb < 8; nb++) {
            o[nb][0] *= al0; o[nb][1] *= al0;
            o[nb][2] *= al1; o[nb][3] *= al1;
        }

#pragma unroll
        for (int kj = 0; kj < 4; kj++) {
            uint32_t pa[4];
            pa[0] = f2h2(s[2 * kj][0], s[2 * kj][1]);
            pa[1] = f2h2(s[2 * kj][2], s[2 * kj][3]);
            pa[2] = f2h2(s[2 * kj + 1][0], s[2 * kj + 1][1]);
            pa[3] = f2h2(s[2 * kj + 1][2], s[2 * kj + 1][3]);

            const uint32_t colb = ((lane >> 4) << 3) * 2;
            uint32_t vf[8][2];
#pragma unroll
            for (int dp = 0; dp < 4; dp++) {
                uint32_t ro = (uint32_t)(kj * 16 + (lane & 15)) * 144 + dp * 32 + colb;
                uint32_t r0, r1, r2, r3;
                ldsm4t(r0, r1, r2, r3, aK + ro);
                vf[dp * 2][0] = r0; vf[dp * 2][1] = r1;
                vf[dp * 2 + 1][0] = r2; vf[dp * 2 + 1][1] = r3;
            }
#pragma unroll
            for (int db = 0; db < 8; db++)
                mma16816(o[db], pa, vf[db][0], vf[db][1]);
        }
    }

    // epilogue -> ssa hi/lo (GEMM2 path keeps split precision)
    const float inv0 = 1.f / l0, inv1 = 1.f / l1;
    const int b = bh >> 4, h = bh & 15;
    const int r0w = q0 + wid * 16 + (lane >> 2);
#pragma unroll
    for (int db = 0; db < 8; db++) {
        const int d = db * 8 + 2 * (lane & 3);
        size_t base0 = ((size_t)b * NN + r0w) * DIMM + h * DHH + d;
        size_t base1 = ((size_t)b * NN + r0w + 8) * DIMM + h * DHH + d;
        uint32_t hi, lo;
        split2(o[db][0] * inv0, o[db][1] * inv0, hi, lo);
        *(uint32_t*)&g_ssa_hi[base0] = hi;
        *(uint32_t*)&g_ssa_lo[base0] = lo;
        split2(o[db][2] * inv1, o[db][3] * inv1, hi, lo);
        *(uint32_t*)&g_ssa_hi[base1] = hi;
        *(uint32_t*)&g_ssa_lo[base1] = lo;
    }
}

// ---------------- launch -----------------------------------------------------
extern "C" void kernel_launch(void* const* d_in, const int* in_sizes, int n_in,
                              void* d_out, int out_size) {
    const float* ZT = (const float*)d_in[0];  // [B, N, DIM]
    const float* W = (const float*)d_in[1];   // [H*DH, DIM]
    float* out = (float*)d_out;               // [B, N, DIM]
    (void)in_sizes; (void)n_in; (void)out_size;

    cudaFuncSetAttribute(gemm1_hmma, cudaFuncAttributeMaxDynamicSharedMemorySize, GEMM1_SMEM);
    cudaFuncSetAttribute(gemm2_hmma, cudaFuncAttributeMaxDynamicSharedMemorySize, GEMM_SMEM);
    cudaFuncSetAttribute(attn_hmma, cudaFuncAttributeMaxDynamicSharedMemorySize, ATTN_SMEM);

    split_zt_kernel<<<(MTOT * DIMM) / (256 * 4), 256>>>(ZT);
    split_w_kernel<<<dim3(32, 32), dim3(32, 32)>>>(W);
    gemm1_hmma<<<dim3(DIMM / 128, MTOT / 128), 256, GEMM1_SMEM>>>();
    attn_hmma<<<dim3(NN / 64, BB * HH), A_THREADS, ATTN_SMEM>>>();
    gemm2_hmma<<<dim3(DIMM / 128, MTOT / 128), 256, GEMM_SMEM>>>(out);
}

// round 17
// speedup vs baseline: 1.9266x; 1.1837x over previous
#include <cuda_runtime.h>
#include <cuda_fp16.h>
#include <stdint.h>
#include <math.h>

#define BB 4
#define NN 2048
#define DIMM 1024
#define HH 16
#define DHH 64
#define SCALE 0.125f
#define MTOT (BB * NN) /* 8192 */
#define S72 72         /* smem row stride in fp16 (144 B, conflict-free ldmatrix) */

// ---------------- fp16 scratch ----------------------------------------------
__device__ __half g_zt[MTOT * DIMM];                           // [m, c] fp16
__device__ __half g_w_hi[DIMM * DIMM], g_w_lo[DIMM * DIMM];    // [kp, c]
__device__ __half g_wt_hi[DIMM * DIMM], g_wt_lo[DIMM * DIMM];  // [c, kp]
__device__ __half g_ztu[MTOT * DIMM];                          // [bh, n, d] fp16
__device__ __half g_ssa[MTOT * DIMM];                          // [m, k] fp16

// ---------------- helpers ---------------------------------------------------
__device__ __forceinline__ uint32_t smem_u32(const void* p) {
    uint32_t a;
    asm("{ .reg .u64 t; cvta.to.shared.u64 t, %1; cvt.u32.u64 %0, t; }" : "=r"(a) : "l"(p));
    return a;
}
__device__ __forceinline__ void cp16(uint32_t dst, const void* src) {
    asm volatile("cp.async.cg.shared.global [%0], [%1], 16;" :: "r"(dst), "l"(src));
}
#define CP_COMMIT() asm volatile("cp.async.commit_group;" ::: "memory")
#define CP_WAIT1() asm volatile("cp.async.wait_group 1;" ::: "memory")
#define CP_WAIT0() asm volatile("cp.async.wait_group 0;" ::: "memory")

__device__ __forceinline__ void ldsm4(uint32_t& r0, uint32_t& r1, uint32_t& r2, uint32_t& r3,
                                      uint32_t addr) {
    asm volatile("ldmatrix.sync.aligned.m8n8.x4.shared.b16 {%0,%1,%2,%3},[%4];"
                 : "=r"(r0), "=r"(r1), "=r"(r2), "=r"(r3) : "r"(addr));
}
__device__ __forceinline__ void ldsm4t(uint32_t& r0, uint32_t& r1, uint32_t& r2, uint32_t& r3,
                                       uint32_t addr) {
    asm volatile("ldmatrix.sync.aligned.m8n8.x4.trans.shared.b16 {%0,%1,%2,%3},[%4];"
                 : "=r"(r0), "=r"(r1), "=r"(r2), "=r"(r3) : "r"(addr));
}
__device__ __forceinline__ void mma16816(float* c, const uint32_t* a, uint32_t b0, uint32_t b1) {
    asm volatile(
        "mma.sync.aligned.m16n8k16.row.col.f32.f16.f16.f32 "
        "{%0,%1,%2,%3},{%4,%5,%6,%7},{%8,%9},{%0,%1,%2,%3};"
        : "+f"(c[0]), "+f"(c[1]), "+f"(c[2]), "+f"(c[3])
        : "r"(a[0]), "r"(a[1]), "r"(a[2]), "r"(a[3]), "r"(b0), "r"(b1));
}
__device__ __forceinline__ uint32_t f2h2(float a, float b) {
    __half2 h = __floats2half2_rn(a, b);
    return *(uint32_t*)&h;
}
__device__ __forceinline__ uint32_t h2scale8(uint32_t x) {  // * 0.125 (exact)
    __half2 v = *(__half2*)&x;
    v = __hmul2(v, __float2half2_rn(0.125f));
    return *(uint32_t*)&v;
}

// ---------------- split kernels ---------------------------------------------
__global__ __launch_bounds__(256) void split_zt_kernel(const float* __restrict__ ZT) {
    size_t i = ((size_t)blockIdx.x * blockDim.x + threadIdx.x) * 4;
    float4 v = *(const float4*)(ZT + i);
    *(uint2*)&g_zt[i] = make_uint2(f2h2(v.x, v.y), f2h2(v.z, v.w));
}

__global__ __launch_bounds__(1024) void split_w_kernel(const float* __restrict__ W) {
    __shared__ float t[32][33];
    int tx = threadIdx.x, ty = threadIdx.y;
    int k = blockIdx.y * 32 + ty, c = blockIdx.x * 32 + tx;
    float v = W[(size_t)k * DIMM + c];
    __half h = __float2half_rn(v);
    g_w_hi[(size_t)k * DIMM + c] = h;
    g_w_lo[(size_t)k * DIMM + c] = __float2half_rn(v - __half2float(h));
    t[ty][tx] = v;
    __syncthreads();
    int k2 = blockIdx.y * 32 + tx, c2 = blockIdx.x * 32 + ty;
    float v2 = t[tx][ty];
    __half h2 = __float2half_rn(v2);
    g_wt_hi[(size_t)c2 * DIMM + k2] = h2;
    g_wt_lo[(size_t)c2 * DIMM + k2] = __float2half_rn(v2 - __half2float(h2));
}

#define G_TILE_B (128 * S72 * 2)    /* 18432 B per tile */
#define G_STAGE_B (3 * G_TILE_B)    /* A, Bh, Bl */
#define GEMM_SMEM (2 * G_STAGE_B)   /* 110592 B -> 2 CTAs/SM */

// ---------------- GEMM1: ZTU = ZT·(Wh+Wl)^T, fp16 A, fp32 acc ---------------
__global__ __launch_bounds__(256) void gemm1_hmma() {
    extern __shared__ char sm[];
    const uint32_t aS = smem_u32(sm);
    const int tid = threadIdx.x, lane = tid & 31, wid = tid >> 5;
    const int wm = wid & 3, wn = wid >> 2;
    const int bm = blockIdx.y * 128, bn = blockIdx.x * 128;

    const __half* gpA = g_zt + (size_t)bm * DIMM;
    const __half* gpBh = g_w_hi + (size_t)bn * DIMM;
    const __half* gpBl = g_w_lo + (size_t)bn * DIMM;

    float c[2][8][4];
#pragma unroll
    for (int mi = 0; mi < 2; mi++)
#pragma unroll
        for (int nb = 0; nb < 8; nb++)
#pragma unroll
            for (int q = 0; q < 4; q++) c[mi][nb][q] = 0.f;

    auto load_stage = [&](int st, int k0) {
        uint32_t sb = aS + (uint32_t)st * G_STAGE_B;
#pragma unroll
        for (int i = 0; i < 4; i++) {
            int idx = tid + i * 256;
            int r = idx >> 3, cc = (idx & 7) * 8;
            uint32_t so = (uint32_t)(r * S72 + cc) * 2;
            size_t go = (size_t)r * DIMM + k0 + cc;
            cp16(sb + 0 * G_TILE_B + so, gpA + go);
            cp16(sb + 1 * G_TILE_B + so, gpBh + go);
            cp16(sb + 2 * G_TILE_B + so, gpBl + go);
        }
    };

    load_stage(0, 0);
    CP_COMMIT();

    for (int ch = 0; ch < 16; ch++) {
        if (ch + 1 < 16) {
            load_stage((ch + 1) & 1, (ch + 1) * 64);
            CP_COMMIT();
            CP_WAIT1();
        } else {
            CP_WAIT0();
        }
        __syncthreads();

        const uint32_t sb = aS + (uint32_t)(ch & 1) * G_STAGE_B;
        const uint32_t aA = sb, aBh = sb + G_TILE_B, aBl = sb + 2 * G_TILE_B;
#pragma unroll
        for (int kd = 0; kd < 4; kd++) {
            const uint32_t colb = (kd * 16 + ((lane >> 4) << 3)) * 2;
            uint32_t af[2][4];
#pragma unroll
            for (int mi = 0; mi < 2; mi++) {
                uint32_t ro = (uint32_t)(wm * 32 + mi * 16 + (lane & 15)) * 144 + colb;
                ldsm4(af[mi][0], af[mi][1], af[mi][2], af[mi][3], aA + ro);
            }
            uint32_t bh[8][2], bl[8][2];
#pragma unroll
            for (int np = 0; np < 4; np++) {
                uint32_t ro = (uint32_t)(wn * 64 + np * 16 + (lane & 15)) * 144 + colb;
                uint32_t r0, r1, r2, r3;
                ldsm4(r0, r1, r2, r3, aBh + ro);
                bh[np * 2][0] = r0; bh[np * 2][1] = r2;
                bh[np * 2 + 1][0] = r1; bh[np * 2 + 1][1] = r3;
                ldsm4(r0, r1, r2, r3, aBl + ro);
                bl[np * 2][0] = r0; bl[np * 2][1] = r2;
                bl[np * 2 + 1][0] = r1; bl[np * 2 + 1][1] = r3;
            }
#pragma unroll
            for (int mi = 0; mi < 2; mi++)
#pragma unroll
                for (int nb = 0; nb < 8; nb++) {
                    mma16816(c[mi][nb], af[mi], bh[nb][0], bh[nb][1]);
                    mma16816(c[mi][nb], af[mi], bl[nb][0], bl[nb][1]);
                }
        }
        __syncthreads();
    }

    // epilogue -> g_ztu fp16 scatter [bh, n, d]
#pragma unroll
    for (int mi = 0; mi < 2; mi++) {
        const int m0 = bm + wm * 32 + mi * 16 + (lane >> 2);
#pragma unroll
        for (int nb = 0; nb < 8; nb++) {
            const int col = bn + wn * 64 + nb * 8 + 2 * (lane & 3);
            const int h = col >> 6, d = col & 63;
#pragma unroll
            for (int rr = 0; rr < 2; rr++) {
                int m = m0 + rr * 8;
                int b = m >> 11, n = m & 2047;
                size_t base = (((size_t)(b * HH + h) * NN) + n) * DHH + d;
                *(uint32_t*)&g_ztu[base] = f2h2(c[mi][nb][rr * 2], c[mi][nb][rr * 2 + 1]);
            }
        }
    }
}

// ---------------- GEMM2: out = SSA·(Wth+Wtl)^T, fp16 A, fp32 out ------------
__global__ __launch_bounds__(256) void gemm2_hmma(float* __restrict__ outp) {
    extern __shared__ char sm[];
    const uint32_t aS = smem_u32(sm);
    const int tid = threadIdx.x, lane = tid & 31, wid = tid >> 5;
    const int wm = wid & 3, wn = wid >> 2;
    const int bm = blockIdx.y * 128, bn = blockIdx.x * 128;

    const __half* gpA = g_ssa + (size_t)bm * DIMM;
    const __half* gpBh = g_wt_hi + (size_t)bn * DIMM;
    const __half* gpBl = g_wt_lo + (size_t)bn * DIMM;

    float c[2][8][4];
#pragma unroll
    for (int mi = 0; mi < 2; mi++)
#pragma unroll
        for (int nb = 0; nb < 8; nb++)
#pragma unroll
            for (int q = 0; q < 4; q++) c[mi][nb][q] = 0.f;

    auto load_stage = [&](int st, int k0) {
        uint32_t sb = aS + (uint32_t)st * G_STAGE_B;
#pragma unroll
        for (int i = 0; i < 4; i++) {
            int idx = tid + i * 256;
            int r = idx >> 3, cc = (idx & 7) * 8;
            uint32_t so = (uint32_t)(r * S72 + cc) * 2;
            size_t go = (size_t)r * DIMM + k0 + cc;
            cp16(sb + 0 * G_TILE_B + so, gpA + go);
            cp16(sb + 1 * G_TILE_B + so, gpBh + go);
            cp16(sb + 2 * G_TILE_B + so, gpBl + go);
        }
    };

    load_stage(0, 0);
    CP_COMMIT();

    for (int ch = 0; ch < 16; ch++) {
        if (ch + 1 < 16) {
            load_stage((ch + 1) & 1, (ch + 1) * 64);
            CP_COMMIT();
            CP_WAIT1();
        } else {
            CP_WAIT0();
        }
        __syncthreads();

        const uint32_t sb = aS + (uint32_t)(ch & 1) * G_STAGE_B;
        const uint32_t aA = sb, aBh = sb + G_TILE_B, aBl = sb + 2 * G_TILE_B;
#pragma unroll
        for (int kd = 0; kd < 4; kd++) {
            const uint32_t colb = (kd * 16 + ((lane >> 4) << 3)) * 2;
            uint32_t af[2][4];
#pragma unroll
            for (int mi = 0; mi < 2; mi++) {
                uint32_t ro = (uint32_t)(wm * 32 + mi * 16 + (lane & 15)) * 144 + colb;
                ldsm4(af[mi][0], af[mi][1], af[mi][2], af[mi][3], aA + ro);
            }
            uint32_t bh[8][2], bl[8][2];
#pragma unroll
            for (int np = 0; np < 4; np++) {
                uint32_t ro = (uint32_t)(wn * 64 + np * 16 + (lane & 15)) * 144 + colb;
                uint32_t r0, r1, r2, r3;
                ldsm4(r0, r1, r2, r3, aBh + ro);
                bh[np * 2][0] = r0; bh[np * 2][1] = r2;
                bh[np * 2 + 1][0] = r1; bh[np * 2 + 1][1] = r3;
                ldsm4(r0, r1, r2, r3, aBl + ro);
                bl[np * 2][0] = r0; bl[np * 2][1] = r2;
                bl[np * 2 + 1][0] = r1; bl[np * 2 + 1][1] = r3;
            }
#pragma unroll
            for (int mi = 0; mi < 2; mi++)
#pragma unroll
                for (int nb = 0; nb < 8; nb++) {
                    mma16816(c[mi][nb], af[mi], bh[nb][0], bh[nb][1]);
                    mma16816(c[mi][nb], af[mi], bl[nb][0], bl[nb][1]);
                }
        }
        __syncthreads();
    }

#pragma unroll
    for (int mi = 0; mi < 2; mi++) {
        const int m0 = bm + wm * 32 + mi * 16 + (lane >> 2);
#pragma unroll
        for (int nb = 0; nb < 8; nb++) {
            const int col = bn + wn * 64 + nb * 8 + 2 * (lane & 3);
            *(float2*)&outp[(size_t)m0 * DIMM + col] = make_float2(c[mi][nb][0], c[mi][nb][1]);
            *(float2*)&outp[(size_t)(m0 + 8) * DIMM + col] = make_float2(c[mi][nb][2], c[mi][nb][3]);
        }
    }
}

// ---------------- HMMA flash attention (fp16 planes, round-13 body) ---------
#define A_KTILE_B (64 * S72 * 2)   /* 9216 B per tile */
#define ATTN_SMEM (3 * A_KTILE_B)  /* 27648 B, 3-stage ring */
#define A_THREADS 128

__global__ __launch_bounds__(A_THREADS) void attn_hmma() {
    extern __shared__ char sm[];
    const uint32_t aK0 = smem_u32(sm);

    const int tid = threadIdx.x, lane = tid & 31, wid = tid >> 5;  // wid 0..3
    const int bh = blockIdx.y, q0 = blockIdx.x * 64;
    const __half* z = g_ztu + (size_t)bh * NN * DHH;

    auto load_k = [&](int st, int j0) {
        uint32_t sb = aK0 + (uint32_t)st * A_KTILE_B;
#pragma unroll
        for (int i = 0; i < 4; i++) {
            int idx = tid + i * A_THREADS;
            int r = idx >> 3, cc = (idx & 7) * 8;
            cp16(sb + (uint32_t)(r * S72 + cc) * 2, z + (size_t)(j0 + r) * DHH + cc);
        }
    };
    load_k(0, 0);
    CP_COMMIT();

    const int qrow = q0 + wid * 16 + (lane >> 2);
    uint32_t qf[4][4];
#pragma unroll
    for (int kd = 0; kd < 4; kd++) {
        const int cb = kd * 16 + 2 * (lane & 3);
        qf[kd][0] = *(const uint32_t*)(z + (size_t)qrow * DHH + cb);
        qf[kd][1] = *(const uint32_t*)(z + (size_t)(qrow + 8) * DHH + cb);
        qf[kd][2] = *(const uint32_t*)(z + (size_t)qrow * DHH + cb + 8);
        qf[kd][3] = *(const uint32_t*)(z + (size_t)(qrow + 8) * DHH + cb + 8);
#pragma unroll
        for (int r = 0; r < 4; r++) qf[kd][r] = h2scale8(qf[kd][r]);
    }

    float o[8][4];
#pragma unroll
    for (int nb = 0; nb < 8; nb++)
#pragma unroll
        for (int q = 0; q < 4; q++) o[nb][q] = 0.f;
    float mr0 = -INFINITY, mr1 = -INFINITY, l0 = 0.f, l1 = 0.f;

    for (int ch = 0; ch < NN / 64; ch++) {
        if (ch + 1 < NN / 64) {
            load_k((ch + 1) % 3, (ch + 1) * 64);
            CP_COMMIT();
            CP_WAIT1();
        } else {
            CP_WAIT0();
        }
        __syncthreads();

        const uint32_t aK = aK0 + (uint32_t)(ch % 3) * A_KTILE_B;

        float s[8][4];
#pragma unroll
        for (int nb = 0; nb < 8; nb++)
#pragma unroll
            for (int q = 0; q < 4; q++) s[nb][q] = 0.f;
#pragma unroll
        for (int kd = 0; kd < 4; kd++) {
            const uint32_t colb = (kd * 16 + ((lane >> 4) << 3)) * 2;
            uint32_t bf[8][2];
#pragma unroll
            for (int np = 0; np < 4; np++) {
                uint32_t ro = (uint32_t)(np * 16 + (lane & 15)) * 144 + colb;
                uint32_t r0, r1, r2, r3;
                ldsm4(r0, r1, r2, r3, aK + ro);
                bf[np * 2][0] = r0; bf[np * 2][1] = r2;
                bf[np * 2 + 1][0] = r1; bf[np * 2 + 1][1] = r3;
            }
#pragma unroll
            for (int nb = 0; nb < 8; nb++)
                mma16816(s[nb], qf[kd], bf[nb][0], bf[nb][1]);
        }

        float t0 = -INFINITY, t1 = -INFINITY;
#pragma unroll
        for (int nb = 0; nb < 8; nb++) {
            t0 = fmaxf(t0, fmaxf(s[nb][0], s[nb][1]));
            t1 = fmaxf(t1, fmaxf(s[nb][2], s[nb][3]));
        }
        t0 = fmaxf(t0, __shfl_xor_sync(0xffffffffu, t0, 1));
        t0 = fmaxf(t0, __shfl_xor_sync(0xffffffffu, t0, 2));
        t1 = fmaxf(t1, __shfl_xor_sync(0xffffffffu, t1, 1));
        t1 = fmaxf(t1, __shfl_xor_sync(0xffffffffu, t1, 2));
        float mn0 = fmaxf(mr0, t0), mn1 = fmaxf(mr1, t1);
        float al0 = __expf(mr0 - mn0), al1 = __expf(mr1 - mn1);
        float ls0 = 0.f, ls1 = 0.f;
#pragma unroll
        for (int nb = 0; nb < 8; nb++) {
            s[nb][0] = __expf(s[nb][0] - mn0);
            s[nb][1] = __expf(s[nb][1] - mn0);
            s[nb][2] = __expf(s[nb][2] - mn1);
            s[nb][3] = __expf(s[nb][3] - mn1);
            ls0 += s[nb][0] + s[nb][1];
            ls1 += s[nb][2] + s[nb][3];
        }
        ls0 += __shfl_xor_sync(0xffffffffu, ls0, 1);
        ls0 += __shfl_xor_sync(0xffffffffu, ls0, 2);
        ls1 += __shfl_xor_sync(0xffffffffu, ls1, 1);
        ls1 += __shfl_xor_sync(0xffffffffu, ls1, 2);
        l0 = l0 * al0 + ls0;
        l1 = l1 * al1 + ls1;
        mr0 = mn0;
        mr1 = mn1;
#pragma unroll
        for (int nb = 0; nb < 8; nb++) {
            o[nb][0] *= al0; o[nb][1] *= al0;
            o[nb][2] *= al1; o[nb][3] *= al1;
        }

#pragma unroll
        for (int kj = 0; kj < 4; kj++) {
            uint32_t pa[4];
            pa[0] = f2h2(s[2 * kj][0], s[2 * kj][1]);
            pa[1] = f2h2(s[2 * kj][2], s[2 * kj][3]);
            pa[2] = f2h2(s[2 * kj + 1][0], s[2 * kj + 1][1]);
            pa[3] = f2h2(s[2 * kj + 1][2], s[2 * kj + 1][3]);

            const uint32_t colb = ((lane >> 4) << 3) * 2;
            uint32_t vf[8][2];
#pragma unroll
            for (int dp = 0; dp < 4; dp++) {
                uint32_t ro = (uint32_t)(kj * 16 + (lane & 15)) * 144 + dp * 32 + colb;
                uint32_t r0, r1, r2, r3;
                ldsm4t(r0, r1, r2, r3, aK + ro);
                vf[dp * 2][0] = r0; vf[dp * 2][1] = r1;
                vf[dp * 2 + 1][0] = r2; vf[dp * 2 + 1][1] = r3;
            }
#pragma unroll
            for (int db = 0; db < 8; db++)
                mma16816(o[db], pa, vf[db][0], vf[db][1]);
        }
    }

    // epilogue -> ssa plain fp16 [b, n, h*64+d]
    const float inv0 = 1.f / l0, inv1 = 1.f / l1;
    const int b = bh >> 4, h = bh & 15;
    const int r0w = q0 + wid * 16 + (lane >> 2);
#pragma unroll
    for (int db = 0; db < 8; db++) {
        const int d = db * 8 + 2 * (lane & 3);
        size_t base0 = ((size_t)b * NN + r0w) * DIMM + h * DHH + d;
        size_t base1 = ((size_t)b * NN + r0w + 8) * DIMM + h * DHH + d;
        *(uint32_t*)&g_ssa[base0] = f2h2(o[db][0] * inv0, o[db][1] * inv0);
        *(uint32_t*)&g_ssa[base1] = f2h2(o[db][2] * inv1, o[db][3] * inv1);
    }
}

// ---------------- launch -----------------------------------------------------
extern "C" void kernel_launch(void* const* d_in, const int* in_sizes, int n_in,
                              void* d_out, int out_size) {
    const float* ZT = (const float*)d_in[0];  // [B, N, DIM]
    const float* W = (const float*)d_in[1];   // [H*DH, DIM]
    float* out = (float*)d_out;               // [B, N, DIM]
    (void)in_sizes; (void)n_in; (void)out_size;

    cudaFuncSetAttribute(gemm1_hmma, cudaFuncAttributeMaxDynamicSharedMemorySize, GEMM_SMEM);
    cudaFuncSetAttribute(gemm2_hmma, cudaFuncAttributeMaxDynamicSharedMemorySize, GEMM_SMEM);
    cudaFuncSetAttribute(attn_hmma, cudaFuncAttributeMaxDynamicSharedMemorySize, ATTN_SMEM);

    split_zt_kernel<<<(MTOT * DIMM) / (256 * 4), 256>>>(ZT);
    split_w_kernel<<<dim3(32, 32), dim3(32, 32)>>>(W);
    gemm1_hmma<<<dim3(DIMM / 128, MTOT / 128), 256, GEMM_SMEM>>>();
    attn_hmma<<<dim3(NN / 64, BB * HH), A_THREADS, ATTN_SMEM>>>();
    gemm2_hmma<<<dim3(DIMM / 128, MTOT / 128), 256, GEMM_SMEM>>>(out);
}